// round 16
// baseline (speedup 1.0000x reference)
#include <cuda_runtime.h>
#include <cuda_bf16.h>
#include <cstdint>

#define NQ 6
#define BATCH 256

__device__ float g_C[2 * 729];
__device__ int g_flag;   // adjoint-done counter (0 -> 2), reset each launch
__device__ int g_done;   // encoder-done counter (0 -> 128), reset each launch

#define L1F 0.99866666666666666f   /* 1 - 4*0.001/3 */
#define L12F 0.98535111111111111f  /* L1 * (1 - 4*0.01/3) */

// bank-conflict swizzle for the 4096-entry Pauli table (GF(2)-linear)
#define SW(i) ((i) ^ (((i) >> 5) & 31))

typedef unsigned long long u64;

// packed dual-fp32 FMA (sm_100+)
__device__ __forceinline__ u64 ffma2(u64 a, u64 b, u64 c) {
    u64 d;
    asm("fma.rn.f32x2 %0, %1, %2, %3;" : "=l"(d) : "l"(a), "l"(b), "l"(c));
    return d;
}

// ---------- adjoint (Heisenberg) pull-based sweeps; symplectic digits I=0,X=1,Z=2,Y=3 ----------

// CNOT conjugation map (involution). Given output slot (i,j), returns source slot
// (si,sj) and the sign of the moved value (evaluated at the source slot, matching
// the push formulation). CA=true -> digit-i side is the control.
__device__ __forceinline__ void cmap(bool CA, int i, int j, int& si, int& sj, int& neg) {
    int dc = CA ? i : j, dt = CA ? j : i;
    int xc = dc & 1, zc = dc >> 1, xt = dt & 1, zt = dt >> 1;
    int ndc = xc | ((zc ^ zt) << 1);
    int ndt = (xt ^ xc) | (zt << 1);
    int oi = CA ? ndc : ndt;
    int oj = CA ? ndt : ndc;
    int sc = CA ? oi : oj, st = CA ? oj : oi;
    neg = (sc & 1) & (st >> 1) & (1 ^ ((sc >> 1) ^ (st & 1)));
    si = oi; sj = oj;
}

// One pull sweep on digit pair (A<B): thread (g,H) computes the 8 output slots
// {i=0..3} x {j=2H,2H+1} of its group from Tin, writes Tout. No internal barrier.
template<int A, int B, bool CB1, bool DBL, bool DEP, bool RAq, bool RBq, int H>
__device__ __forceinline__ void sweepP(const float* Tin, float* Tout,
                                       const float* Ma, const float* Mb, int g) {
    constexpr int lo = 2 * A, hi = 2 * B;
    int mv1 = (1 << lo) - 1;
    int t1 = ((g & ~mv1) << 2) | (g & mv1);
    int mv2 = (1 << hi) - 1;
    int base = ((t1 & ~mv2) << 2) | (t1 & mv2);
    int tb = 4 * SW(base);
    const char* Ti = (const char*)Tin;
    char* To = (char*)Tout;

    float l00 = 1.f, l01 = 1.f, l10 = 1.f, l11 = 1.f;
    if (DEP) {
        float fixed = 1.f;
#pragma unroll
        for (int q = 0; q < 6; q++) {
            if (q == A || q == B) continue;
            if ((base >> (2 * q)) & 3) fixed *= (q == 5 ? L1F : L12F);
        }
        const float la = (A == 5 ? L1F : L12F), lb = (B == 5 ? L1F : L12F);
        l00 = fixed; l10 = fixed * la; l01 = fixed * lb; l11 = fixed * la * lb;
    }

    // gather w[i2][j2] (signed + depol-scaled, pulled through the CNOT(s))
    float w[4][4];
#pragma unroll
    for (int i2 = 0; i2 < 4; i2++) {
#pragma unroll
        for (int j2 = 0; j2 < 4; j2++) {
            bool need = RBq ? (H == 0 ? true : (j2 >= 1))
                            : (j2 == 2 * H || j2 == 2 * H + 1);
            if (!need) continue;
            int si = i2, sj = j2, neg = 0;
            if (DBL) { int a, b, n; cmap(CB1, si, sj, a, b, n); si = a; sj = b; neg ^= n; }
            { int a, b, n; cmap(!CB1, si, sj, a, b, n); si = a; sj = b; neg ^= n; }
            float val = *(const float*)(Ti + (tb ^ (4 * SW((si << lo) | (sj << hi)))));
            float f;
            if (DEP) {
                float l = si ? (sj ? l11 : l10) : (sj ? l01 : l00);
                f = l * val;
                if (neg) f = -f;
            } else {
                f = neg ? -val : val;
            }
            w[i2][j2] = f;
        }
    }

    // stage 1: RB mixes digit-B (j); rows j=1,2,3 use Mb[0..2],[3..5],[6..8]
    float u0[4], u1[4];   // owned j = 2H and 2H+1
    if (RBq) {
        float b0a = 0.f, b1a = 0.f, b2a = 0.f;
        if (H == 1) { b0a = Mb[3]; b1a = Mb[4]; b2a = Mb[5]; }       // row j=2
        float b0b = Mb[6 * H + 0], b1b = Mb[6 * H + 1], b2b = Mb[6 * H + 2];  // H=0: j=1; H=1: j=3
#pragma unroll
        for (int i2 = 0; i2 < 4; i2++) {
            u0[i2] = (H == 0) ? w[i2][0]
                              : fmaf(b0a, w[i2][1], fmaf(b1a, w[i2][2], b2a * w[i2][3]));
            u1[i2] = fmaf(b0b, w[i2][1], fmaf(b1b, w[i2][2], b2b * w[i2][3]));
        }
    } else {
#pragma unroll
        for (int i2 = 0; i2 < 4; i2++) { u0[i2] = w[i2][2 * H]; u1[i2] = w[i2][2 * H + 1]; }
    }

    // stage 2: RA mixes digit-A (i)
    float o0[4], o1[4];
    if (RAq) {
        float a0 = Ma[0], a1 = Ma[1], a2 = Ma[2], a3 = Ma[3], a4 = Ma[4];
        float a5 = Ma[5], a6 = Ma[6], a7 = Ma[7], a8 = Ma[8];
        o0[0] = u0[0]; o1[0] = u1[0];
        o0[1] = fmaf(a0, u0[1], fmaf(a1, u0[2], a2 * u0[3]));
        o0[2] = fmaf(a3, u0[1], fmaf(a4, u0[2], a5 * u0[3]));
        o0[3] = fmaf(a6, u0[1], fmaf(a7, u0[2], a8 * u0[3]));
        o1[1] = fmaf(a0, u1[1], fmaf(a1, u1[2], a2 * u1[3]));
        o1[2] = fmaf(a3, u1[1], fmaf(a4, u1[2], a5 * u1[3]));
        o1[3] = fmaf(a6, u1[1], fmaf(a7, u1[2], a8 * u1[3]));
    } else {
#pragma unroll
        for (int i = 0; i < 4; i++) { o0[i] = u0[i]; o1[i] = u1[i]; }
    }

#pragma unroll
    for (int i = 0; i < 4; i++) {
        *(float*)(To + (tb ^ (4 * SW((i << lo) | ((2 * H) << hi)))))     = o0[i];
        *(float*)(To + (tb ^ (4 * SW((i << lo) | ((2 * H + 1) << hi))))) = o1[i];
    }
}

// uniform barrier + H-dispatch + buffer swap
#define DO_SWEEP(A_, B_, CB1_, DBL_, DEP_, RA_, RB_, Mav, Mbv)                      \
    do {                                                                            \
        __syncthreads();                                                            \
        if (hwarp) sweepP<A_, B_, CB1_, DBL_, DEP_, RA_, RB_, 1>(c, n, Mav, Mbv, g);\
        else       sweepP<A_, B_, CB1_, DBL_, DEP_, RA_, RB_, 0>(c, n, Mav, Mbv, g);\
        float* _t = c; c = n; n = _t;                                               \
    } while (0)

// ---------------- single fused kernel, 512 threads/block ----------------
// blocks 0..127: encoder (2 batch rows) -> spin on g_flag -> contract -> out
// blocks 128,129: adjoint Heisenberg evolution (512 active threads, pull sweeps)
__global__ __launch_bounds__(512, 1) void fused_all_kernel(
    const float* __restrict__ x, const float* __restrict__ W1, const float* __restrict__ b1,
    const float* __restrict__ ln_g, const float* __restrict__ ln_b,
    const float* __restrict__ W2, const float* __restrict__ b2,
    const float* __restrict__ shared_w, const float* __restrict__ task_w,
    const float* __restrict__ Wp, const float* __restrict__ bp,
    float* __restrict__ out)
{
    __shared__ __align__(16) float SM[8464];   // adjoint: Ta[4096] + Tb[4096] + MA[272]
    int tid = threadIdx.x;
    int lane = tid & 31, warp = tid >> 5;

    if (blockIdx.x < 128) {
        // ======== encoder: 2 batch rows per block, 16 warps, coalesced W1 ========
        int b0 = blockIdx.x * 2;
        float* hs = SM;              // [2][256]
        float* red = SM + 512;       // 16
        float* stat = SM + 528;      // 2
        float* stat2 = SM + 530;     // 2
        float* zs = SM + 532;        // [2][6]
        float* u = SM + 544;         // [2][3][9] = 54
        float* cred = SM + 600;      // [16][2]

        ulonglong2 xq[2][6];
        u64 xt[2];
#pragma unroll
        for (int r = 0; r < 2; r++) {
            const ulonglong2* xg = (const ulonglong2*)(x + (size_t)(b0 + r) * 784);
#pragma unroll
            for (int i = 0; i < 6; i++) xq[r][i] = xg[lane + 32 * i];
            xt[r] = (lane < 8) ? *(const u64*)(x + (size_t)(b0 + r) * 784 + 768 + 2 * lane) : 0ULL;
        }

        for (int j = 0; j < 16; j++) {
            int row = warp * 16 + j;
            const ulonglong2* wg = (const ulonglong2*)(W1 + (size_t)row * 784);
            ulonglong2 wq[6];
#pragma unroll
            for (int i = 0; i < 6; i++) wq[i] = wg[lane + 32 * i];
            u64 wt = (lane < 8) ? *(const u64*)(W1 + (size_t)row * 784 + 768 + 2 * lane) : 0ULL;
            u64 p0 = 0ULL, p1 = 0ULL;
#pragma unroll
            for (int i = 0; i < 6; i++) {
                u64 wx = wq[i].x, wy = wq[i].y;
                p0 = ffma2(wx, xq[0][i].x, p0); p0 = ffma2(wy, xq[0][i].y, p0);
                p1 = ffma2(wx, xq[1][i].x, p1); p1 = ffma2(wy, xq[1][i].y, p1);
            }
            p0 = ffma2(wt, xt[0], p0);
            p1 = ffma2(wt, xt[1], p1);
            float2 f0 = *(float2*)&p0, f1 = *(float2*)&p1;
            float a0 = f0.x + f0.y, a1 = f1.x + f1.y;
#pragma unroll
            for (int o = 16; o > 0; o >>= 1) {
                a0 += __shfl_xor_sync(0xffffffffu, a0, o);
                a1 += __shfl_xor_sync(0xffffffffu, a1, o);
            }
            if (lane == 0) {
                float bv = b1[row];
                hs[row] = fmaxf(a0 + bv, 0.f);
                hs[256 + row] = fmaxf(a1 + bv, 0.f);
            }
        }
        __syncthreads();

        // ---- LayerNorm over 256 elements (threads 0..255 active) ----
        float h0 = 0.f, h1 = 0.f;
        if (tid < 256) {
            h0 = hs[tid];
            h1 = hs[256 + tid];
            float t0 = h0, t1 = h1;
#pragma unroll
            for (int o = 16; o > 0; o >>= 1) {
                t0 += __shfl_xor_sync(0xffffffffu, t0, o);
                t1 += __shfl_xor_sync(0xffffffffu, t1, o);
            }
            if (lane == 0) { red[warp] = t0; red[8 + warp] = t1; }
        }
        __syncthreads();
        if (tid < 2) {
            float s = 0.f;
#pragma unroll
            for (int w = 0; w < 8; w++) s += red[tid * 8 + w];
            stat[tid] = s * (1.f / 256.f);
        }
        __syncthreads();
        float d0 = h0 - stat[0], d1 = h1 - stat[1];
        if (tid < 256) {
            float t0 = d0 * d0, t1 = d1 * d1;
#pragma unroll
            for (int o = 16; o > 0; o >>= 1) {
                t0 += __shfl_xor_sync(0xffffffffu, t0, o);
                t1 += __shfl_xor_sync(0xffffffffu, t1, o);
            }
            if (lane == 0) { red[warp] = t0; red[8 + warp] = t1; }
        }
        __syncthreads();
        if (tid < 2) {
            float s = 0.f;
#pragma unroll
            for (int w = 0; w < 8; w++) s += red[tid * 8 + w];
            stat2[tid] = rsqrtf(s * (1.f / 256.f) + 1e-5f);
        }
        __syncthreads();
        if (tid < 256) {
            float g = ln_g[tid], be = ln_b[tid];
            hs[tid] = fmaf(d0 * stat2[0], g, be);
            hs[256 + tid] = fmaf(d1 * stat2[1], g, be);
        }
        __syncthreads();

        // z = tanh(h @ W2^T + b2): 12 (row, j) pairs over warps 0..11
        if (warp < 12) {
            int r = warp / 6, j = warp - r * 6;
            const float* hr = hs + r * 256;
            const float* wj = W2 + j * 256;
            float s = 0.f;
#pragma unroll
            for (int t2_ = lane; t2_ < 256; t2_ += 32) s = fmaf(hr[t2_], wj[t2_], s);
#pragma unroll
            for (int o = 16; o > 0; o >>= 1) s += __shfl_xor_sync(0xffffffffu, s, o);
            if (lane == 0) zs[r * 6 + j] = tanhf(s + b2[j]);
        }

        // ---- wait for adjoint blocks (g_C ready) ----
        if (tid == 0) {
            while (*(volatile int*)&g_flag < 2) { }
        }
        __syncthreads();
        __threadfence();

        // ---- contraction for this block's 2 rows ----
        if (tid < 54) {
            int r = tid / 27, rem = tid % 27, p = rem / 9, ij = rem % 9;
            int i = ij % 3, jj = ij / 3;
            float sa, ca, sb, cb;
            __sincosf(3.14159265358979323846f * zs[r * 6 + 2 * p], &sa, &ca);
            __sincosf(3.14159265358979323846f * zs[r * 6 + 2 * p + 1], &sb, &cb);
            float vi = (i == 0) ? 1.f : ((i == 1) ? L1F * sa : L1F * ca);
            float vj = (jj == 0) ? 1.f : ((jj == 1) ? L1F * sb : L1F * cb);
            u[r * 27 + p * 9 + ij] = vi * vj;
        }
        __syncthreads();

        {
            int r = warp >> 3;                 // 8 warps per row
            const float* ur = u + r * 27;
            float acc0 = 0.f, acc1 = 0.f;
            for (int s = lane + 32 * (warp & 7); s < 729; s += 256) {
                int i01 = s % 9, q9 = s / 9;
                int i23 = q9 % 9, i45 = q9 / 9;
                float w = ur[i01] * ur[9 + i23] * ur[18 + i45];
                acc0 = fmaf(g_C[s], w, acc0);
                acc1 = fmaf(g_C[729 + s], w, acc1);
            }
#pragma unroll
            for (int o = 16; o > 0; o >>= 1) {
                acc0 += __shfl_xor_sync(0xffffffffu, acc0, o);
                acc1 += __shfl_xor_sync(0xffffffffu, acc1, o);
            }
            if (lane == 0) { cred[warp * 2] = acc0; cred[warp * 2 + 1] = acc1; }
        }
        __syncthreads();
        if (tid < 4) {
            int r = tid >> 1, o = tid & 1;
            float s = bp[o];
#pragma unroll
            for (int w = 0; w < 8; w++) s += cred[(8 * r + w) * 2 + o];
            out[(b0 + r) * 2 + o] = s;
        }
        __syncthreads();
        if (tid == 0) {
            int v = atomicAdd(&g_done, 1);
            if (v == 127) { g_done = 0; g_flag = 0; }
        }
    } else {
        // ======== adjoint Heisenberg evolution for O_op = sum_i Wp[op,i] Z_i ========
        int op = blockIdx.x - 128;
        float* Ta = SM;            // buffer 0
        float* Tb = SM + 4096;     // buffer 1
        float* MA = SM + 8192;     // 30 x 9 adjoint Bloch matrices (XZY basis)

        int g = tid & 255;         // group index
        bool hwarp = tid >= 256;   // half ownership (warp-uniform)

        if (tid < 30) {
            const float* w = (tid < 18) ? (shared_w + tid * 3) : (task_w + (tid - 18) * 3);
            float a = -w[0], b = -w[1], gg = -w[2];
            float ca, sa, cb, sb, cg, sg;
            sincosf(a, &sa, &ca);
            sincosf(b, &sb, &cb);
            sincosf(gg, &sg, &cg);
            float A00 = ca * cb * cg - sa * sg;
            float A01 = -ca * cb * sg - sa * cg;
            float A02 = ca * sb;
            float A10 = sa * cb * cg + ca * sg;
            float A11 = -sa * cb * sg + ca * cg;
            float A12 = sa * sb;
            float A20 = -sb * cg;
            float A21 = sb * sg;
            float A22 = cb;
            float* M = MA + tid * 9;   // order (X,Z,Y) = XYZ rows/cols (0,2,1)
            M[0] = A00; M[1] = A02; M[2] = A01;
            M[3] = A20; M[4] = A22; M[5] = A21;
            M[6] = A10; M[7] = A12; M[8] = A11;
        }
#pragma unroll
        for (int k = 0; k < 8; k++) Ta[tid + 512 * k] = 0.f;
        __syncthreads();
        if (tid < 6) Ta[SW(2 << (2 * tid))] = L1F * Wp[op * NQ + tid];

        float* c = Ta;
        float* n = Tb;

        // adjoint order: task l=1 (r=2), task l=0 (r=1), depol + shared l=2 (r=3),
        //                shared l=1 (r=2), shared l=0 (r=1)
        for (int it = 0; it < 2; it++) {
            const float* M2 = MA + (it ? 6 : 24) * 9;
            DO_SWEEP(1, 5, true,  false, false, false, false, M2, M2);
            DO_SWEEP(3, 5, false, false, false, false, true,  M2, M2 + 5 * 9);
            DO_SWEEP(1, 3, false, false, false, true,  true,  M2 + 1 * 9, M2 + 3 * 9);
            DO_SWEEP(0, 4, true,  false, false, false, false, M2, M2);
            DO_SWEEP(2, 4, false, false, false, false, true,  M2, M2 + 4 * 9);
            DO_SWEEP(0, 2, false, false, false, true,  true,  M2 + 0 * 9, M2 + 2 * 9);
            const float* M1 = MA + (it ? 0 : 18) * 9;
            DO_SWEEP(0, 5, true,  false, false, false, false, M1, M1);
            DO_SWEEP(4, 5, false, false, false, false, true,  M1, M1 + 5 * 9);
            DO_SWEEP(3, 4, false, false, false, false, true,  M1, M1 + 4 * 9);
            DO_SWEEP(2, 3, false, false, false, false, true,  M1, M1 + 3 * 9);
            DO_SWEEP(1, 2, false, false, false, false, true,  M1, M1 + 2 * 9);
            DO_SWEEP(0, 1, false, false, false, true,  true,  M1 + 0 * 9, M1 + 1 * 9);
            if (it == 0) {
                const float* M3 = MA + 12 * 9;
                DO_SWEEP(2, 5, true, true, true,  true, true, M3 + 2 * 9, M3 + 5 * 9);
                DO_SWEEP(1, 4, true, true, false, true, true, M3 + 1 * 9, M3 + 4 * 9);
                DO_SWEEP(0, 3, true, true, false, true, true, M3 + 0 * 9, M3 + 3 * 9);
            }
        }
        __syncthreads();

        // write Y-free strings compacted to base-3 index (final data in c)
#pragma unroll
        for (int k = 0; k < 8; k++) {
            int s = tid + 512 * k;
            if ((s & (s >> 1) & 0x555) == 0) {
                int s3 = 0;
#pragma unroll
                for (int q = 5; q >= 0; q--) s3 = s3 * 3 + ((s >> (2 * q)) & 3);
                g_C[op * 729 + s3] = c[SW(s)];
            }
        }
        __threadfence();
        __syncthreads();
        if (tid == 0) atomicAdd(&g_flag, 1);
    }
}

extern "C" void kernel_launch(void* const* d_in, const int* in_sizes, int n_in,
                              void* d_out, int out_size) {
    const float* x        = (const float*)d_in[0];
    const float* W1       = (const float*)d_in[1];
    const float* b1       = (const float*)d_in[2];
    const float* ln_g     = (const float*)d_in[3];
    const float* ln_b     = (const float*)d_in[4];
    const float* W2       = (const float*)d_in[5];
    const float* b2       = (const float*)d_in[6];
    const float* shared_w = (const float*)d_in[7];
    const float* task_w   = (const float*)d_in[8];
    const float* Wp       = (const float*)d_in[9];
    const float* bp       = (const float*)d_in[10];
    float* out = (float*)d_out;

    fused_all_kernel<<<130, 512>>>(x, W1, b1, ln_g, ln_b, W2, b2,
                                   shared_w, task_w, Wp, bp, out);
}